// round 12
// baseline (speedup 1.0000x reference)
#include <cuda_runtime.h>
#include <cstdint>

namespace {
constexpr int L        = 512;
constexpr int C        = 128;
constexpr int F        = 128;
constexpr int Kw       = 7;
constexpr int L_OUT    = L - Kw + 1;   // 506
constexpr int KC       = Kw * C;       // 896
constexpr int BK       = 64;           // K chunk
constexpr int BN       = 64;           // N half per CTA
constexpr int NCHUNK   = KC / BK;      // 14
constexpr int A_STRIDE = BK + 4;       // 68 floats -> conflict-free A frag loads
constexpr int B_STRIDE = BN + 8;       // 72 floats -> conflict-free B frag loads
constexpr int A_STAGE_ELE = 128 * A_STRIDE;  // 8704
constexpr int B_STAGE_ELE = BK * B_STRIDE;   // 4608
constexpr size_t SMEM_BYTES = (size_t)2 * (A_STAGE_ELE + B_STAGE_ELE) * 4; // 106496
constexpr int NTHREADS = 128;          // 4 warps along M; each warp 32Mx64N
}

__device__ __forceinline__ uint32_t f2tf(float f) {
    uint32_t r;
    asm("cvt.rna.tf32.f32 %0, %1;" : "=r"(r) : "f"(f));
    return r;
}

__device__ __forceinline__ void mma_tf32(float* c, const uint32_t* a, const uint32_t* b) {
    asm volatile(
        "mma.sync.aligned.m16n8k8.row.col.f32.tf32.tf32.f32 "
        "{%0,%1,%2,%3},{%4,%5,%6,%7},{%8,%9},{%0,%1,%2,%3};"
        : "+f"(c[0]), "+f"(c[1]), "+f"(c[2]), "+f"(c[3])
        : "r"(a[0]), "r"(a[1]), "r"(a[2]), "r"(a[3]), "r"(b[0]), "r"(b[1]));
}

__global__ void __launch_bounds__(NTHREADS, 2)
LocalBlock_kernel(const float* __restrict__ x, const float* __restrict__ w,
                  const float* __restrict__ bias, const float* __restrict__ gamma,
                  const float* __restrict__ beta, const float* __restrict__ mean,
                  const float* __restrict__ var, float* __restrict__ out)
{
    extern __shared__ float smem[];
    float* As = smem;                                 // [2][128][A_STRIDE]
    float* Bs = smem + 2 * A_STAGE_ELE;               // [2][BK][B_STRIDE]
    __shared__ float s_inv[BN];
    __shared__ float s_cst[BN];

    const int l    = blockIdx.x;
    const int nb   = blockIdx.y * BN;                 // N-half base (0 or 64)
    const int tid  = threadIdx.x;

    if (tid < BN) {
        int g = nb + tid;
        float iv = gamma[g] * rsqrtf(var[g] + 1e-3f);
        s_inv[tid] = iv;
        s_cst[tid] = bias[(size_t)l * F + g] * iv + beta[g] - mean[g] * iv;
    }

    const float* xb = x + (size_t)l * C;              // A[b][k] = xb[b*L*C + k]
    const float* wb = w + (size_t)l * KC * F + nb;    // B[k][fl]

    const uint32_t sA = (uint32_t)__cvta_generic_to_shared(As);
    const uint32_t sB = (uint32_t)__cvta_generic_to_shared(Bs);

    auto load_stage = [&](int stage, int kc0) {
        const uint32_t sa = sA + stage * A_STAGE_ELE * 4;
        const uint32_t sb = sB + stage * B_STAGE_ELE * 4;
        // A chunk: 128 rows x 64 floats = 2048 float4 -> 16 per thread
        #pragma unroll
        for (int i = 0; i < 16; i++) {
            int idx = tid + i * NTHREADS;
            int row = idx >> 4;
            int c4  = (idx & 15) << 2;
            const float* g = xb + (size_t)row * (L * C) + kc0 + c4;
            asm volatile("cp.async.cg.shared.global [%0], [%1], 16;"
                         :: "r"(sa + (row * A_STRIDE + c4) * 4), "l"(g));
        }
        // B chunk: 64 rows x 64 floats = 1024 float4 -> 8 per thread
        #pragma unroll
        for (int i = 0; i < 8; i++) {
            int idx = tid + i * NTHREADS;
            int row = idx >> 4;
            int c4  = (idx & 15) << 2;
            const float* g = wb + (size_t)(kc0 + row) * F + c4;
            asm volatile("cp.async.cg.shared.global [%0], [%1], 16;"
                         :: "r"(sb + (row * B_STRIDE + c4) * 4), "l"(g));
        }
        asm volatile("cp.async.commit_group;");
    };

    load_stage(0, 0);   // prologue

    const int warp = tid >> 5, lane = tid & 31;
    const int wm = warp * 32;
    const int g4 = lane >> 2, t4 = lane & 3;

    float acc[2][8][4];
    #pragma unroll
    for (int mi = 0; mi < 2; mi++)
        #pragma unroll
        for (int ni = 0; ni < 8; ni++)
            #pragma unroll
            for (int q = 0; q < 4; q++) acc[mi][ni][q] = 0.f;

    uint32_t aF[2][2][4], bF[2][8][2];   // double-buffered fragments

    auto load_frag = [&](const float* As_s, const float* Bs_s, int k8, int buf) {
        const int kb = k8 * 8;
        #pragma unroll
        for (int mi = 0; mi < 2; mi++) {
            const float* ap = As_s + (wm + mi * 16 + g4) * A_STRIDE + kb + t4;
            aF[buf][mi][0] = f2tf(ap[0]);
            aF[buf][mi][1] = f2tf(ap[8 * A_STRIDE]);
            aF[buf][mi][2] = f2tf(ap[4]);
            aF[buf][mi][3] = f2tf(ap[8 * A_STRIDE + 4]);
        }
        #pragma unroll
        for (int ni = 0; ni < 8; ni++) {
            const float* bp = Bs_s + (kb + t4) * B_STRIDE + ni * 8 + g4;
            bF[buf][ni][0] = f2tf(bp[0]);
            bF[buf][ni][1] = f2tf(bp[4 * B_STRIDE]);
        }
    };

    for (int kt = 0; kt < NCHUNK; kt++) {
        asm volatile("cp.async.wait_group 0;");
        __syncthreads();   // chunk kt resident; all warps done with kt-1 -> its stage free

        if (kt + 1 < NCHUNK)
            load_stage((kt + 1) & 1, (kt + 1) * BK);   // overlaps with compute below

        const float* As_s = As + (kt & 1) * A_STAGE_ELE;
        const float* Bs_s = Bs + (kt & 1) * B_STAGE_ELE;

        load_frag(As_s, Bs_s, 0, 0);
        #pragma unroll
        for (int k8 = 0; k8 < 8; k8++) {
            const int cur = k8 & 1;
            if (k8 < 7) load_frag(As_s, Bs_s, k8 + 1, cur ^ 1);
            #pragma unroll
            for (int mi = 0; mi < 2; mi++)
                #pragma unroll
                for (int ni = 0; ni < 8; ni++)
                    mma_tf32(acc[mi][ni], aF[cur][mi], bF[cur][ni]);
        }
    }

    // Epilogue: BN affine + ReLU, write out[b][l][nb+col]
    #pragma unroll
    for (int mi = 0; mi < 2; mi++) {
        const int r0 = wm + mi * 16 + g4;
        #pragma unroll
        for (int ni = 0; ni < 8; ni++) {
            const int col = ni * 8 + t4 * 2;
            const float i0 = s_inv[col], i1 = s_inv[col + 1];
            const float k0 = s_cst[col], k1 = s_cst[col + 1];
            float v0 = fmaxf(fmaf(acc[mi][ni][0], i0, k0), 0.f);
            float v1 = fmaxf(fmaf(acc[mi][ni][1], i1, k1), 0.f);
            float v2 = fmaxf(fmaf(acc[mi][ni][2], i0, k0), 0.f);
            float v3 = fmaxf(fmaf(acc[mi][ni][3], i1, k1), 0.f);
            float2* o0 = (float2*)(out + (size_t)r0 * (L_OUT * F) + (size_t)l * F + nb + col);
            float2* o1 = (float2*)(out + (size_t)(r0 + 8) * (L_OUT * F) + (size_t)l * F + nb + col);
            *o0 = make_float2(v0, v1);
            *o1 = make_float2(v2, v3);
        }
    }
}

extern "C" void kernel_launch(void* const* d_in, const int* in_sizes, int n_in,
                              void* d_out, int out_size)
{
    (void)in_sizes; (void)n_in; (void)out_size;
    const float* x     = (const float*)d_in[0];
    const float* w     = (const float*)d_in[1];
    const float* bias  = (const float*)d_in[2];
    const float* gamma = (const float*)d_in[3];
    const float* beta  = (const float*)d_in[4];
    const float* mean  = (const float*)d_in[5];
    const float* var   = (const float*)d_in[6];
    float* out = (float*)d_out;

    cudaFuncSetAttribute(LocalBlock_kernel,
                         cudaFuncAttributeMaxDynamicSharedMemorySize,
                         (int)SMEM_BYTES);
    dim3 grid(L_OUT, 2);
    LocalBlock_kernel<<<grid, NTHREADS, SMEM_BYTES>>>(x, w, bias, gamma, beta, mean, var, out);
}

// round 13
// speedup vs baseline: 1.0710x; 1.0710x over previous
#include <cuda_runtime.h>
#include <cstdint>

namespace {
constexpr int L        = 512;
constexpr int C        = 128;
constexpr int F        = 128;
constexpr int Kw       = 7;
constexpr int L_OUT    = L - Kw + 1;   // 506
constexpr int KC       = Kw * C;       // 896
constexpr int BK       = 32;           // K chunk (small -> small smem -> 4 CTAs/SM)
constexpr int BN       = 64;           // N half per CTA
constexpr int NCHUNK   = KC / BK;      // 28
constexpr int A_STRIDE = BK + 4;       // 36 floats -> conflict-free A frag loads
constexpr int B_STRIDE = BN + 8;       // 72 floats -> conflict-free B frag loads
constexpr int A_STAGE_ELE = 128 * A_STRIDE;  // 4608
constexpr int B_STAGE_ELE = BK * B_STRIDE;   // 2304
constexpr size_t SMEM_BYTES = (size_t)2 * (A_STAGE_ELE + B_STAGE_ELE) * 4; // 55296
constexpr int NTHREADS = 128;          // 4 warps along M; each warp 32Mx64N
}

__device__ __forceinline__ uint32_t f2tf(float f) {
    uint32_t r;
    asm("cvt.rna.tf32.f32 %0, %1;" : "=r"(r) : "f"(f));
    return r;
}

__device__ __forceinline__ void mma_tf32(float* c, const uint32_t* a, const uint32_t* b) {
    asm volatile(
        "mma.sync.aligned.m16n8k8.row.col.f32.tf32.tf32.f32 "
        "{%0,%1,%2,%3},{%4,%5,%6,%7},{%8,%9},{%0,%1,%2,%3};"
        : "+f"(c[0]), "+f"(c[1]), "+f"(c[2]), "+f"(c[3])
        : "r"(a[0]), "r"(a[1]), "r"(a[2]), "r"(a[3]), "r"(b[0]), "r"(b[1]));
}

__global__ void __launch_bounds__(NTHREADS, 4)
LocalBlock_kernel(const float* __restrict__ x, const float* __restrict__ w,
                  const float* __restrict__ bias, const float* __restrict__ gamma,
                  const float* __restrict__ beta, const float* __restrict__ mean,
                  const float* __restrict__ var, float* __restrict__ out)
{
    extern __shared__ float smem[];
    float* As = smem;                                 // [2][128][A_STRIDE]
    float* Bs = smem + 2 * A_STAGE_ELE;               // [2][BK][B_STRIDE]
    __shared__ float s_inv[BN];
    __shared__ float s_cst[BN];

    const int l    = blockIdx.x;
    const int nb   = blockIdx.y * BN;                 // N-half base (0 or 64)
    const int tid  = threadIdx.x;

    if (tid < BN) {
        int g = nb + tid;
        float iv = gamma[g] * rsqrtf(var[g] + 1e-3f);
        s_inv[tid] = iv;
        s_cst[tid] = bias[(size_t)l * F + g] * iv + beta[g] - mean[g] * iv;
    }

    const float* xb = x + (size_t)l * C;              // A[b][k] = xb[b*L*C + k]
    const float* wb = w + (size_t)l * KC * F + nb;    // B[k][fl]

    const uint32_t sA = (uint32_t)__cvta_generic_to_shared(As);
    const uint32_t sB = (uint32_t)__cvta_generic_to_shared(Bs);

    auto load_stage = [&](int stage, int kc0) {
        const uint32_t sa = sA + stage * A_STAGE_ELE * 4;
        const uint32_t sb = sB + stage * B_STAGE_ELE * 4;
        // A chunk: 128 rows x 32 floats = 1024 float4 -> 8 per thread
        #pragma unroll
        for (int i = 0; i < 8; i++) {
            int idx = tid + i * NTHREADS;
            int row = idx >> 3;
            int c4  = (idx & 7) << 2;
            const float* g = xb + (size_t)row * (L * C) + kc0 + c4;
            asm volatile("cp.async.cg.shared.global [%0], [%1], 16;"
                         :: "r"(sa + (row * A_STRIDE + c4) * 4), "l"(g));
        }
        // B chunk: 32 rows x 64 floats = 512 float4 -> 4 per thread
        #pragma unroll
        for (int i = 0; i < 4; i++) {
            int idx = tid + i * NTHREADS;
            int row = idx >> 4;
            int c4  = (idx & 15) << 2;
            const float* g = wb + (size_t)(kc0 + row) * F + c4;
            asm volatile("cp.async.cg.shared.global [%0], [%1], 16;"
                         :: "r"(sb + (row * B_STRIDE + c4) * 4), "l"(g));
        }
        asm volatile("cp.async.commit_group;");
    };

    load_stage(0, 0);   // prologue

    const int warp = tid >> 5, lane = tid & 31;
    const int wm = warp * 32;
    const int g4 = lane >> 2, t4 = lane & 3;

    float acc[2][8][4];
    #pragma unroll
    for (int mi = 0; mi < 2; mi++)
        #pragma unroll
        for (int ni = 0; ni < 8; ni++)
            #pragma unroll
            for (int q = 0; q < 4; q++) acc[mi][ni][q] = 0.f;

    for (int kt = 0; kt < NCHUNK; kt++) {
        asm volatile("cp.async.wait_group 0;");
        __syncthreads();   // chunk kt resident; all warps done with kt-1 -> its stage free

        if (kt + 1 < NCHUNK)
            load_stage((kt + 1) & 1, (kt + 1) * BK);   // overlaps with compute below

        const float* As_s = As + (kt & 1) * A_STAGE_ELE;
        const float* Bs_s = Bs + (kt & 1) * B_STAGE_ELE;

        #pragma unroll
        for (int k8 = 0; k8 < BK / 8; k8++) {
            const int kb = k8 * 8;
            uint32_t a[2][4], b[8][2];
            #pragma unroll
            for (int mi = 0; mi < 2; mi++) {
                const float* ap = As_s + (wm + mi * 16 + g4) * A_STRIDE + kb + t4;
                a[mi][0] = f2tf(ap[0]);
                a[mi][1] = f2tf(ap[8 * A_STRIDE]);
                a[mi][2] = f2tf(ap[4]);
                a[mi][3] = f2tf(ap[8 * A_STRIDE + 4]);
            }
            #pragma unroll
            for (int ni = 0; ni < 8; ni++) {
                const float* bp = Bs_s + (kb + t4) * B_STRIDE + ni * 8 + g4;
                b[ni][0] = f2tf(bp[0]);
                b[ni][1] = f2tf(bp[4 * B_STRIDE]);
            }
            #pragma unroll
            for (int mi = 0; mi < 2; mi++)
                #pragma unroll
                for (int ni = 0; ni < 8; ni++)
                    mma_tf32(acc[mi][ni], a[mi], b[ni]);
        }
    }

    // Epilogue: BN affine + ReLU, write out[b][l][nb+col]
    #pragma unroll
    for (int mi = 0; mi < 2; mi++) {
        const int r0 = wm + mi * 16 + g4;
        #pragma unroll
        for (int ni = 0; ni < 8; ni++) {
            const int col = ni * 8 + t4 * 2;
            const float i0 = s_inv[col], i1 = s_inv[col + 1];
            const float k0 = s_cst[col], k1 = s_cst[col + 1];
            float v0 = fmaxf(fmaf(acc[mi][ni][0], i0, k0), 0.f);
            float v1 = fmaxf(fmaf(acc[mi][ni][1], i1, k1), 0.f);
            float v2 = fmaxf(fmaf(acc[mi][ni][2], i0, k0), 0.f);
            float v3 = fmaxf(fmaf(acc[mi][ni][3], i1, k1), 0.f);
            float2* o0 = (float2*)(out + (size_t)r0 * (L_OUT * F) + (size_t)l * F + nb + col);
            float2* o1 = (float2*)(out + (size_t)(r0 + 8) * (L_OUT * F) + (size_t)l * F + nb + col);
            *o0 = make_float2(v0, v1);
            *o1 = make_float2(v2, v3);
        }
    }
}

extern "C" void kernel_launch(void* const* d_in, const int* in_sizes, int n_in,
                              void* d_out, int out_size)
{
    (void)in_sizes; (void)n_in; (void)out_size;
    const float* x     = (const float*)d_in[0];
    const float* w     = (const float*)d_in[1];
    const float* bias  = (const float*)d_in[2];
    const float* gamma = (const float*)d_in[3];
    const float* beta  = (const float*)d_in[4];
    const float* mean  = (const float*)d_in[5];
    const float* var   = (const float*)d_in[6];
    float* out = (float*)d_out;

    cudaFuncSetAttribute(LocalBlock_kernel,
                         cudaFuncAttributeMaxDynamicSharedMemorySize,
                         (int)SMEM_BYTES);
    dim3 grid(L_OUT, 2);
    LocalBlock_kernel<<<grid, NTHREADS, SMEM_BYTES>>>(x, w, bias, gamma, beta, mean, var, out);
}